// round 4
// baseline (speedup 1.0000x reference)
#include <cuda_runtime.h>
#include <math.h>

#define Nn 1024
#define Ff 64
#define ALPHA 0.2f

// scratch
__device__ float g_Wh[Nn * Ff];
__device__ float g_e1[Nn];
__device__ float g_e2[Nn];
__device__ float g_part[4][Nn * Ff];
__device__ float g_dsum[4][Nn];

// ---------------------------------------------------------------------------
// kA: Wh = h @ W ; e1 = Wh@a1 ; e2 = Wh@a2. grid 256 (4 rows/block).
// No SMEM staging of W: coalesced L2 reads with deep MLP, no entry barrier.
// ---------------------------------------------------------------------------
__global__ __launch_bounds__(256) void gat_kA(const float* __restrict__ h,
                                              const float* __restrict__ W,
                                              const float* __restrict__ a) {
    __shared__ float es1[8], es2[8];
    int t = threadIdx.x;
    int row0 = blockIdx.x * 4;
    int ii = t >> 6;          // 0..3
    int f  = t & 63;
    int row = row0 + ii;

    const float* hrow = h + row * Ff;
    float acc = 0.f;
#pragma unroll
    for (int k = 0; k < Ff; k++)
        acc += __ldg(&hrow[k]) * __ldg(&W[k * Ff + f]);
    g_Wh[row * Ff + f] = acc;

    float p1 = acc * __ldg(&a[f]);
    float p2 = acc * __ldg(&a[Ff + f]);
#pragma unroll
    for (int o = 16; o; o >>= 1) {
        p1 += __shfl_xor_sync(0xffffffffu, p1, o);
        p2 += __shfl_xor_sync(0xffffffffu, p2, o);
    }
    int w = t >> 5;
    if ((t & 31) == 0) { es1[w] = p1; es2[w] = p2; }
    __syncthreads();
    if (t < 4) {
        g_e1[row0 + t] = es1[2 * t] + es1[2 * t + 1];
        g_e2[row0 + t] = es2[2 * t] + es2[2 * t + 1];
    }
}

// ---------------------------------------------------------------------------
// kC: unnormalized-softmax weighted partial GEMM + partial denominators.
// grid = 128 rowgroups x 4 jsplits = 512 blocks, 256 threads.
// Block (rg, js): rows rg*8..+8, j in [js*256, +256).
// w_ij = adj ? exp(leakyrelu(e1_i+e2_j)) : 0   (no max-sub: scores bounded)
// p stored PRE-DUPLICATED in SMEM as {p,p} u64 pairs (stride 20 floats) so
// the GEMM inner loop is 1 LDG.128 + 4 broadcast LDS.128 + 16 fma.f32x2.
// Per-block row sums of w go to g_dsum[js]; partial out to g_part[js].
// ---------------------------------------------------------------------------
__global__ __launch_bounds__(256) void gat_kC(const int* __restrict__ adj) {
    __shared__ float ps[256 * 20];      // [j][ii-pair-duplicated], 20KB
    __shared__ float4 red4[1024];       // 16KB tree buffer
    __shared__ float e1s[8];

    int t = threadIdx.x;
    int rg = blockIdx.x >> 2;
    int js = blockIdx.x & 3;
    int r0 = rg * 8;
    int jbase = js * 256;
    int w = t >> 5, l = t & 31;

    if (t < 8) e1s[t] = g_e1[r0 + t];
    __syncthreads();

    // ---- p tile: thread t owns column j = jbase + t (8 rows) ----
    {
        float e2v = __ldg(&g_e2[jbase + t]);
        float pv[8];
#pragma unroll
        for (int ii = 0; ii < 8; ii++) {
            int av = __ldg(&adj[(size_t)(r0 + ii) * Nn + jbase + t]);
            float sc = e1s[ii] + e2v;
            sc = (sc > 0.f) ? sc : ALPHA * sc;
            pv[ii] = (av > 0) ? __expf(sc) : 0.f;
        }
        float* base = &ps[t * 20];
        *(float4*)(base + 0)  = make_float4(pv[0], pv[0], pv[1], pv[1]);
        *(float4*)(base + 4)  = make_float4(pv[2], pv[2], pv[3], pv[3]);
        *(float4*)(base + 8)  = make_float4(pv[4], pv[4], pv[5], pv[5]);
        *(float4*)(base + 12) = make_float4(pv[6], pv[6], pv[7], pv[7]);
    }
    __syncthreads();

    // ---- partial denominators: warp w sums row w over this j-chunk ----
    {
        float dsum = 0.f;
#pragma unroll
        for (int k = 0; k < 8; k++)
            dsum += ps[(l + k * 32) * 20 + 2 * w];
#pragma unroll
        for (int o = 16; o; o >>= 1)
            dsum += __shfl_xor_sync(0xffffffffu, dsum, o);
        if (l == 0) g_dsum[js][r0 + w] = dsum;
    }

    // ---- register-tile GEMM: thread (fi, jg), 16 j's each ----
    int fi = t & 15;
    int jg = t >> 4;
    const float4* WhL = (const float4*)(g_Wh + (size_t)jbase * Ff);

    unsigned long long acc_lo[8], acc_hi[8];
#pragma unroll
    for (int i = 0; i < 8; i++) { acc_lo[i] = 0ull; acc_hi[i] = 0ull; }

#pragma unroll 4
    for (int k = 0; k < 16; k++) {
        int j = k * 16 + jg;
        float4 wh = WhL[j * 16 + fi];
        const float* pb = &ps[j * 20];
        ulonglong2 pA = *(const ulonglong2*)(pb + 0);
        ulonglong2 pB = *(const ulonglong2*)(pb + 4);
        ulonglong2 pC = *(const ulonglong2*)(pb + 8);
        ulonglong2 pD = *(const ulonglong2*)(pb + 12);
        unsigned long long wlo, whi;
        asm("mov.b64 %0,{%1,%2};" : "=l"(wlo) : "r"(__float_as_uint(wh.x)), "r"(__float_as_uint(wh.y)));
        asm("mov.b64 %0,{%1,%2};" : "=l"(whi) : "r"(__float_as_uint(wh.z)), "r"(__float_as_uint(wh.w)));
        asm("fma.rn.f32x2 %0,%1,%2,%0;" : "+l"(acc_lo[0]) : "l"(pA.x), "l"(wlo));
        asm("fma.rn.f32x2 %0,%1,%2,%0;" : "+l"(acc_hi[0]) : "l"(pA.x), "l"(whi));
        asm("fma.rn.f32x2 %0,%1,%2,%0;" : "+l"(acc_lo[1]) : "l"(pA.y), "l"(wlo));
        asm("fma.rn.f32x2 %0,%1,%2,%0;" : "+l"(acc_hi[1]) : "l"(pA.y), "l"(whi));
        asm("fma.rn.f32x2 %0,%1,%2,%0;" : "+l"(acc_lo[2]) : "l"(pB.x), "l"(wlo));
        asm("fma.rn.f32x2 %0,%1,%2,%0;" : "+l"(acc_hi[2]) : "l"(pB.x), "l"(whi));
        asm("fma.rn.f32x2 %0,%1,%2,%0;" : "+l"(acc_lo[3]) : "l"(pB.y), "l"(wlo));
        asm("fma.rn.f32x2 %0,%1,%2,%0;" : "+l"(acc_hi[3]) : "l"(pB.y), "l"(whi));
        asm("fma.rn.f32x2 %0,%1,%2,%0;" : "+l"(acc_lo[4]) : "l"(pC.x), "l"(wlo));
        asm("fma.rn.f32x2 %0,%1,%2,%0;" : "+l"(acc_hi[4]) : "l"(pC.x), "l"(whi));
        asm("fma.rn.f32x2 %0,%1,%2,%0;" : "+l"(acc_lo[5]) : "l"(pC.y), "l"(wlo));
        asm("fma.rn.f32x2 %0,%1,%2,%0;" : "+l"(acc_hi[5]) : "l"(pC.y), "l"(whi));
        asm("fma.rn.f32x2 %0,%1,%2,%0;" : "+l"(acc_lo[6]) : "l"(pD.x), "l"(wlo));
        asm("fma.rn.f32x2 %0,%1,%2,%0;" : "+l"(acc_hi[6]) : "l"(pD.x), "l"(whi));
        asm("fma.rn.f32x2 %0,%1,%2,%0;" : "+l"(acc_lo[7]) : "l"(pD.y), "l"(wlo));
        asm("fma.rn.f32x2 %0,%1,%2,%0;" : "+l"(acc_hi[7]) : "l"(pD.y), "l"(whi));
    }

    float af[8][4];
#pragma unroll
    for (int ii = 0; ii < 8; ii++) {
        float2 lo = *(float2*)&acc_lo[ii];
        float2 hi = *(float2*)&acc_hi[ii];
        af[ii][0] = lo.x; af[ii][1] = lo.y; af[ii][2] = hi.x; af[ii][3] = hi.y;
    }

    // ---- tree reduction over 16 jg splits ----
    __syncthreads();
#pragma unroll
    for (int sh = 8; sh >= 1; sh >>= 1) {
        if (jg >= sh && jg < 2 * sh) {
            float4* dst = &red4[((jg - sh) * 16 + fi) * 8];
#pragma unroll
            for (int ii = 0; ii < 8; ii++)
                dst[ii] = make_float4(af[ii][0], af[ii][1], af[ii][2], af[ii][3]);
        }
        __syncthreads();
        if (jg < sh) {
            const float4* sp = &red4[(jg * 16 + fi) * 8];
#pragma unroll
            for (int ii = 0; ii < 8; ii++) {
                float4 v = sp[ii];
                af[ii][0] += v.x; af[ii][1] += v.y; af[ii][2] += v.z; af[ii][3] += v.w;
            }
        }
        __syncthreads();
    }

    if (jg == 0) {
        float4* dst = (float4*)g_part[js];
#pragma unroll
        for (int ii = 0; ii < 8; ii++)
            dst[(r0 + ii) * 16 + fi] = make_float4(af[ii][0], af[ii][1], af[ii][2], af[ii][3]);
    }
}

// ---------------------------------------------------------------------------
// kD: sum 4 partials, normalize by summed denominator, elu. grid 128 x 128.
// ---------------------------------------------------------------------------
__global__ __launch_bounds__(128) void gat_kD(float* __restrict__ out) {
    int idx = blockIdx.x * 128 + threadIdx.x;   // 0..16383
    int i = idx >> 4;                           // row
    float4 v0 = ((const float4*)g_part[0])[idx];
    float4 v1 = ((const float4*)g_part[1])[idx];
    float4 v2 = ((const float4*)g_part[2])[idx];
    float4 v3 = ((const float4*)g_part[3])[idx];
    float d = (g_dsum[0][i] + g_dsum[1][i]) + (g_dsum[2][i] + g_dsum[3][i]);
    float inv = 1.0f / d;
    float4 v;
    v.x = ((v0.x + v1.x) + (v2.x + v3.x)) * inv;
    v.y = ((v0.y + v1.y) + (v2.y + v3.y)) * inv;
    v.z = ((v0.z + v1.z) + (v2.z + v3.z)) * inv;
    v.w = ((v0.w + v1.w) + (v2.w + v3.w)) * inv;
    v.x = (v.x > 0.f) ? v.x : expm1f(v.x);
    v.y = (v.y > 0.f) ? v.y : expm1f(v.y);
    v.z = (v.z > 0.f) ? v.z : expm1f(v.z);
    v.w = (v.w > 0.f) ? v.w : expm1f(v.w);
    ((float4*)out)[idx] = v;
}

// ---------------------------------------------------------------------------
extern "C" void kernel_launch(void* const* d_in, const int* in_sizes, int n_in,
                              void* d_out, int out_size) {
    const float* h   = (const float*)d_in[0];
    const int*   adj = (const int*)d_in[1];
    const float* W   = (const float*)d_in[2];
    const float* a   = (const float*)d_in[3];
    float* out = (float*)d_out;

    gat_kA<<<256, 256>>>(h, W, a);
    gat_kC<<<512, 256>>>(adj);
    gat_kD<<<128, 128>>>(out);
}

// round 5
// speedup vs baseline: 1.5000x; 1.5000x over previous
#include <cuda_runtime.h>
#include <math.h>

#define Nn 1024
#define Ff 64
#define ALPHA 0.2f

// scratch
__device__ float g_Wh[Nn * Ff];
__device__ float g_e1[Nn];
__device__ float g_e2[Nn];

// ---------------------------------------------------------------------------
// k1: Wh = h @ W ; e1 = Wh@a1 ; e2 = Wh@a2. grid 256 (4 rows/block),
// SMEM-staged W (16KB), 1 output/thread.
// ---------------------------------------------------------------------------
__global__ __launch_bounds__(256) void gat_k1(const float* __restrict__ h,
                                              const float* __restrict__ W,
                                              const float* __restrict__ a) {
    __shared__ float Ws[Ff * Ff];
    __shared__ float hs[4 * Ff];
    __shared__ float a1s[Ff], a2s[Ff];
    __shared__ float es1[8], es2[8];
    int t = threadIdx.x;
    int row0 = blockIdx.x * 4;

#pragma unroll
    for (int k = 0; k < 4; k++)
        ((float4*)Ws)[t + k * 256] = ((const float4*)W)[t + k * 256];
    hs[t] = h[row0 * Ff + t];
    if (t < Ff) { a1s[t] = a[t]; a2s[t] = a[Ff + t]; }
    __syncthreads();

    int ii = t >> 6;
    int f  = t & 63;
    float acc = 0.f;
#pragma unroll
    for (int k = 0; k < Ff; k++)
        acc += hs[ii * Ff + k] * Ws[k * Ff + f];
    int row = row0 + ii;
    g_Wh[row * Ff + f] = acc;

    float p1 = acc * a1s[f];
    float p2 = acc * a2s[f];
#pragma unroll
    for (int o = 16; o; o >>= 1) {
        p1 += __shfl_xor_sync(0xffffffffu, p1, o);
        p2 += __shfl_xor_sync(0xffffffffu, p2, o);
    }
    int w = t >> 5;
    if ((t & 31) == 0) { es1[w] = p1; es2[w] = p2; }
    __syncthreads();
    if (t < 4) {
        g_e1[row0 + t] = es1[2 * t] + es1[2 * t + 1];
        g_e2[row0 + t] = es2[2 * t] + es2[2 * t + 1];
    }
}

// ---------------------------------------------------------------------------
// k2: fully fused attention: out = elu( (P@Wh) / rowsum ).
// grid 256 (4 rows/block, full j range), 256 threads.
// Unnormalized softmax: w_ij = adj ? exp(leakyrelu(e1_i+e2_j)) : 0.
// 4 j-tiles of 256. p stored pre-duplicated {p,p} pairs, stride 12 floats
// (48B: 16B-aligned, conflict-free at quarter-warp granularity).
// GEMM thread (fi=t&15, jg=t>>4): 4-row x 4-col register tile, 16 j per
// tile, Wh via LDG.128 (L1/L2). Denominators accumulated inline.
// Epilogue: 16-split SMEM reduction + normalize + elu + store. One launch.
// ---------------------------------------------------------------------------
__global__ __launch_bounds__(256) void gat_k2(const int* __restrict__ adj,
                                              float* __restrict__ out) {
    __shared__ float ps[256 * 12];        // 12KB: p-tile, dup pairs
    __shared__ float red[16 * 264];       // 16.5KB: split-reduction buffer
    __shared__ float e1s[4];
    __shared__ float wpart[8 * 4];        // per-warp dsum partials

    int t = threadIdx.x;
    int r0 = blockIdx.x * 4;
    int w = t >> 5, l = t & 31;
    int fi = t & 15;
    int jg = t >> 4;

    if (t < 4) e1s[t] = g_e1[r0 + t];
    __syncthreads();

    float dls0 = 0.f, dls1 = 0.f, dls2 = 0.f, dls3 = 0.f;
    unsigned long long acc_lo[4], acc_hi[4];
#pragma unroll
    for (int i = 0; i < 4; i++) { acc_lo[i] = 0ull; acc_hi[i] = 0ull; }

    const float4* WhL = (const float4*)g_Wh;

#pragma unroll 1
    for (int jt = 0; jt < 4; jt++) {
        int jbase = jt * 256;
        __syncthreads();                  // protect ps reuse

        // ---- p tile: thread t -> column j = jbase + t, 4 rows ----
        {
            int j = jbase + t;
            float e2v = __ldg(&g_e2[j]);
            const int* acol = adj + j;
            int a0 = __ldg(&acol[(size_t)(r0 + 0) * Nn]);
            int a1 = __ldg(&acol[(size_t)(r0 + 1) * Nn]);
            int a2 = __ldg(&acol[(size_t)(r0 + 2) * Nn]);
            int a3 = __ldg(&acol[(size_t)(r0 + 3) * Nn]);
            float s0 = e1s[0] + e2v; s0 = (s0 > 0.f) ? s0 : ALPHA * s0;
            float s1 = e1s[1] + e2v; s1 = (s1 > 0.f) ? s1 : ALPHA * s1;
            float s2 = e1s[2] + e2v; s2 = (s2 > 0.f) ? s2 : ALPHA * s2;
            float s3 = e1s[3] + e2v; s3 = (s3 > 0.f) ? s3 : ALPHA * s3;
            float p0 = (a0 > 0) ? __expf(s0) : 0.f;
            float p1 = (a1 > 0) ? __expf(s1) : 0.f;
            float p2 = (a2 > 0) ? __expf(s2) : 0.f;
            float p3 = (a3 > 0) ? __expf(s3) : 0.f;
            dls0 += p0; dls1 += p1; dls2 += p2; dls3 += p3;
            float* base = &ps[t * 12];
            *(float4*)(base + 0) = make_float4(p0, p0, p1, p1);
            *(float4*)(base + 4) = make_float4(p2, p2, p3, p3);
        }
        __syncthreads();

        // ---- GEMM: 16 j's for this (fi, jg) ----
#pragma unroll 4
        for (int k = 0; k < 16; k++) {
            int j = k * 16 + jg;
            float4 wh = WhL[(jbase + j) * 16 + fi];
            ulonglong2 pA = *(const ulonglong2*)&ps[j * 12];
            ulonglong2 pB = *(const ulonglong2*)&ps[j * 12 + 4];
            unsigned long long wlo, whi;
            asm("mov.b64 %0,{%1,%2};" : "=l"(wlo) : "r"(__float_as_uint(wh.x)), "r"(__float_as_uint(wh.y)));
            asm("mov.b64 %0,{%1,%2};" : "=l"(whi) : "r"(__float_as_uint(wh.z)), "r"(__float_as_uint(wh.w)));
            asm("fma.rn.f32x2 %0,%1,%2,%0;" : "+l"(acc_lo[0]) : "l"(pA.x), "l"(wlo));
            asm("fma.rn.f32x2 %0,%1,%2,%0;" : "+l"(acc_hi[0]) : "l"(pA.x), "l"(whi));
            asm("fma.rn.f32x2 %0,%1,%2,%0;" : "+l"(acc_lo[1]) : "l"(pA.y), "l"(wlo));
            asm("fma.rn.f32x2 %0,%1,%2,%0;" : "+l"(acc_hi[1]) : "l"(pA.y), "l"(whi));
            asm("fma.rn.f32x2 %0,%1,%2,%0;" : "+l"(acc_lo[2]) : "l"(pB.x), "l"(wlo));
            asm("fma.rn.f32x2 %0,%1,%2,%0;" : "+l"(acc_hi[2]) : "l"(pB.x), "l"(whi));
            asm("fma.rn.f32x2 %0,%1,%2,%0;" : "+l"(acc_lo[3]) : "l"(pB.y), "l"(wlo));
            asm("fma.rn.f32x2 %0,%1,%2,%0;" : "+l"(acc_hi[3]) : "l"(pB.y), "l"(whi));
        }
    }

    // ---- denominator: warp-reduce then per-warp partials ----
#pragma unroll
    for (int o = 16; o; o >>= 1) {
        dls0 += __shfl_xor_sync(0xffffffffu, dls0, o);
        dls1 += __shfl_xor_sync(0xffffffffu, dls1, o);
        dls2 += __shfl_xor_sync(0xffffffffu, dls2, o);
        dls3 += __shfl_xor_sync(0xffffffffu, dls3, o);
    }
    if (l == 0) {
        wpart[w * 4 + 0] = dls0;
        wpart[w * 4 + 1] = dls1;
        wpart[w * 4 + 2] = dls2;
        wpart[w * 4 + 3] = dls3;
    }

    // ---- write register tiles to red[jg][ii*64 + fi*4 + c] ----
#pragma unroll
    for (int ii = 0; ii < 4; ii++) {
        float2 lo = *(float2*)&acc_lo[ii];
        float2 hi = *(float2*)&acc_hi[ii];
        *(float4*)&red[jg * 264 + ii * 64 + fi * 4] = make_float4(lo.x, lo.y, hi.x, hi.y);
    }
    __syncthreads();

    // ---- final: thread t owns output element t of the 4x64 block tile ----
    {
        int ii = t >> 6;
        float d = 0.f;
#pragma unroll
        for (int k = 0; k < 8; k++) d += wpart[k * 4 + ii];
        float inv = 1.0f / d;

        float val = 0.f;
#pragma unroll
        for (int g = 0; g < 16; g++) val += red[g * 264 + t];
        val *= inv;
        val = (val > 0.f) ? val : expm1f(val);
        out[(size_t)(r0 + ii) * Ff + (t & 63)] = val;
    }
}

// ---------------------------------------------------------------------------
extern "C" void kernel_launch(void* const* d_in, const int* in_sizes, int n_in,
                              void* d_out, int out_size) {
    const float* h   = (const float*)d_in[0];
    const int*   adj = (const int*)d_in[1];
    const float* W   = (const float*)d_in[2];
    const float* a   = (const float*)d_in[3];
    float* out = (float*)d_out;

    gat_k1<<<256, 256>>>(h, W, a);
    gat_k2<<<256, 256>>>(adj, out);
}

// round 6
// speedup vs baseline: 1.9108x; 1.2739x over previous
#include <cuda_runtime.h>
#include <math.h>

#define Nn 1024
#define Ff 64
#define ALPHA 0.2f

// scratch
__device__ float g_Wh[Nn * Ff];
__device__ float g_e1[Nn];
__device__ float g_e2[Nn];

// ---------------------------------------------------------------------------
// k1: Wh = h @ W ; e1 = Wh@a1 ; e2 = Wh@a2. grid 256 (4 rows/block),
// SMEM-staged W (16KB), 1 output/thread.
// ---------------------------------------------------------------------------
__global__ __launch_bounds__(256) void gat_k1(const float* __restrict__ h,
                                              const float* __restrict__ W,
                                              const float* __restrict__ a) {
    __shared__ float Ws[Ff * Ff];
    __shared__ float hs[4 * Ff];
    __shared__ float a1s[Ff], a2s[Ff];
    __shared__ float es1[8], es2[8];
    int t = threadIdx.x;
    int row0 = blockIdx.x * 4;

#pragma unroll
    for (int k = 0; k < 4; k++)
        ((float4*)Ws)[t + k * 256] = ((const float4*)W)[t + k * 256];
    hs[t] = h[row0 * Ff + t];
    if (t < Ff) { a1s[t] = a[t]; a2s[t] = a[Ff + t]; }
    __syncthreads();

    int ii = t >> 6;
    int f  = t & 63;
    float acc = 0.f;
#pragma unroll
    for (int k = 0; k < Ff; k++)
        acc += hs[ii * Ff + k] * Ws[k * Ff + f];
    int row = row0 + ii;
    g_Wh[row * Ff + f] = acc;

    float p1 = acc * a1s[f];
    float p2 = acc * a2s[f];
#pragma unroll
    for (int o = 16; o; o >>= 1) {
        p1 += __shfl_xor_sync(0xffffffffu, p1, o);
        p2 += __shfl_xor_sync(0xffffffffu, p2, o);
    }
    int w = t >> 5;
    if ((t & 31) == 0) { es1[w] = p1; es2[w] = p2; }
    __syncthreads();
    if (t < 4) {
        g_e1[row0 + t] = es1[2 * t] + es1[2 * t + 1];
        g_e2[row0 + t] = es2[2 * t] + es2[2 * t + 1];
    }
}

// ---------------------------------------------------------------------------
// k2: fused attention: out = elu( (P@Wh) / rowsum ), unnormalized softmax.
// grid 256 (4 rows/block, full j range), 256 threads.
// Latency plan:
//  - ALL adj (16) + e2 (4) loads hoisted to kernel entry -> regs (MLP ~20).
//  - Wh LDG.128 double-buffered in register batches of 4 (prefetch k+1 batch
//    and next tile's batch 0 during FMAs) -> ~8 loads in flight.
//  - p pre-duplicated {p,p} pairs in SMEM (stride 12), 2 broadcast LDS.128
//    per 16-j step.
// ---------------------------------------------------------------------------
__global__ __launch_bounds__(256) void gat_k2(const int* __restrict__ adj,
                                              float* __restrict__ out) {
    __shared__ float ps[256 * 12];        // 12KB p-tile (dup pairs)
    __shared__ float red[16 * 264];       // 16.5KB split-reduction buffer
    __shared__ float e1s[4];
    __shared__ float wpart[8 * 4];

    int t = threadIdx.x;
    int r0 = blockIdx.x * 4;
    int w = t >> 5, l = t & 31;
    int fi = t & 15;
    int jg = t >> 4;

    // ---- hoisted loads: adj[4 tiles][4 rows], e2[4 tiles] ----
    int av[4][4];
    float e2v[4];
#pragma unroll
    for (int jt = 0; jt < 4; jt++) {
#pragma unroll
        for (int ii = 0; ii < 4; ii++)
            av[jt][ii] = __ldg(&adj[(size_t)(r0 + ii) * Nn + jt * 256 + t]);
        e2v[jt] = __ldg(&g_e2[jt * 256 + t]);
    }
    if (t < 4) e1s[t] = g_e1[r0 + t];
    __syncthreads();

    float dls0 = 0.f, dls1 = 0.f, dls2 = 0.f, dls3 = 0.f;
    unsigned long long acc_lo[4], acc_hi[4];
#pragma unroll
    for (int i = 0; i < 4; i++) { acc_lo[i] = 0ull; acc_hi[i] = 0ull; }

    const float4* WhL = (const float4*)g_Wh;

    // prefetch first Wh batch (tile 0, k=0..3)
    float4 whbuf[4];
#pragma unroll
    for (int kk = 0; kk < 4; kk++)
        whbuf[kk] = WhL[(kk * 16 + jg) * 16 + fi];

#pragma unroll
    for (int jt = 0; jt < 4; jt++) {
        int jbase = jt * 256;
        __syncthreads();                  // ps reuse guard

        // ---- p tile from preloaded regs ----
        {
            float e2 = e2v[jt];
            float s0 = e1s[0] + e2; s0 = (s0 > 0.f) ? s0 : ALPHA * s0;
            float s1 = e1s[1] + e2; s1 = (s1 > 0.f) ? s1 : ALPHA * s1;
            float s2 = e1s[2] + e2; s2 = (s2 > 0.f) ? s2 : ALPHA * s2;
            float s3 = e1s[3] + e2; s3 = (s3 > 0.f) ? s3 : ALPHA * s3;
            float p0 = (av[jt][0] > 0) ? __expf(s0) : 0.f;
            float p1 = (av[jt][1] > 0) ? __expf(s1) : 0.f;
            float p2 = (av[jt][2] > 0) ? __expf(s2) : 0.f;
            float p3 = (av[jt][3] > 0) ? __expf(s3) : 0.f;
            dls0 += p0; dls1 += p1; dls2 += p2; dls3 += p3;
            float* base = &ps[t * 12];
            *(float4*)(base + 0) = make_float4(p0, p0, p1, p1);
            *(float4*)(base + 4) = make_float4(p2, p2, p3, p3);
        }
        __syncthreads();

        // ---- GEMM: 16 j-steps in 4 double-buffered batches ----
#pragma unroll
        for (int kb = 0; kb < 4; kb++) {
            float4 c[4];
#pragma unroll
            for (int kk = 0; kk < 4; kk++) c[kk] = whbuf[kk];

            if (kb < 3) {
#pragma unroll
                for (int kk = 0; kk < 4; kk++)
                    whbuf[kk] = WhL[(jbase + ((kb + 1) * 4 + kk) * 16 + jg) * 16 + fi];
            } else if (jt < 3) {
#pragma unroll
                for (int kk = 0; kk < 4; kk++)
                    whbuf[kk] = WhL[(jbase + 256 + kk * 16 + jg) * 16 + fi];
            }

#pragma unroll
            for (int kk = 0; kk < 4; kk++) {
                int j = (kb * 4 + kk) * 16 + jg;
                float4 wh = c[kk];
                ulonglong2 pA = *(const ulonglong2*)&ps[j * 12];
                ulonglong2 pB = *(const ulonglong2*)&ps[j * 12 + 4];
                unsigned long long wlo, whi;
                asm("mov.b64 %0,{%1,%2};" : "=l"(wlo) : "r"(__float_as_uint(wh.x)), "r"(__float_as_uint(wh.y)));
                asm("mov.b64 %0,{%1,%2};" : "=l"(whi) : "r"(__float_as_uint(wh.z)), "r"(__float_as_uint(wh.w)));
                asm("fma.rn.f32x2 %0,%1,%2,%0;" : "+l"(acc_lo[0]) : "l"(pA.x), "l"(wlo));
                asm("fma.rn.f32x2 %0,%1,%2,%0;" : "+l"(acc_hi[0]) : "l"(pA.x), "l"(whi));
                asm("fma.rn.f32x2 %0,%1,%2,%0;" : "+l"(acc_lo[1]) : "l"(pA.y), "l"(wlo));
                asm("fma.rn.f32x2 %0,%1,%2,%0;" : "+l"(acc_hi[1]) : "l"(pA.y), "l"(whi));
                asm("fma.rn.f32x2 %0,%1,%2,%0;" : "+l"(acc_lo[2]) : "l"(pB.x), "l"(wlo));
                asm("fma.rn.f32x2 %0,%1,%2,%0;" : "+l"(acc_hi[2]) : "l"(pB.x), "l"(whi));
                asm("fma.rn.f32x2 %0,%1,%2,%0;" : "+l"(acc_lo[3]) : "l"(pB.y), "l"(wlo));
                asm("fma.rn.f32x2 %0,%1,%2,%0;" : "+l"(acc_hi[3]) : "l"(pB.y), "l"(whi));
            }
        }
    }

    // ---- denominator reduction ----
#pragma unroll
    for (int o = 16; o; o >>= 1) {
        dls0 += __shfl_xor_sync(0xffffffffu, dls0, o);
        dls1 += __shfl_xor_sync(0xffffffffu, dls1, o);
        dls2 += __shfl_xor_sync(0xffffffffu, dls2, o);
        dls3 += __shfl_xor_sync(0xffffffffu, dls3, o);
    }
    if (l == 0) {
        wpart[w * 4 + 0] = dls0;
        wpart[w * 4 + 1] = dls1;
        wpart[w * 4 + 2] = dls2;
        wpart[w * 4 + 3] = dls3;
    }

    // ---- write register tiles ----
#pragma unroll
    for (int ii = 0; ii < 4; ii++) {
        float2 lo = *(float2*)&acc_lo[ii];
        float2 hi = *(float2*)&acc_hi[ii];
        *(float4*)&red[jg * 264 + ii * 64 + fi * 4] = make_float4(lo.x, lo.y, hi.x, hi.y);
    }
    __syncthreads();

    // ---- final: thread t -> output element t of the 4x64 tile ----
    {
        int ii = t >> 6;
        float d = 0.f;
#pragma unroll
        for (int k = 0; k < 8; k++) d += wpart[k * 4 + ii];
        float inv = 1.0f / d;

        float val = 0.f;
#pragma unroll
        for (int g = 0; g < 16; g++) val += red[g * 264 + t];
        val *= inv;
        val = (val > 0.f) ? val : expm1f(val);
        out[(size_t)(r0 + ii) * Ff + (t & 63)] = val;
    }
}

// ---------------------------------------------------------------------------
extern "C" void kernel_launch(void* const* d_in, const int* in_sizes, int n_in,
                              void* d_out, int out_size) {
    const float* h   = (const float*)d_in[0];
    const int*   adj = (const int*)d_in[1];
    const float* W   = (const float*)d_in[2];
    const float* a   = (const float*)d_in[3];
    float* out = (float*)d_out;

    gat_k1<<<256, 256>>>(h, W, a);
    gat_k2<<<256, 256>>>(adj, out);
}